// round 5
// baseline (speedup 1.0000x reference)
#include <cuda_runtime.h>
#include <cuda_bf16.h>
#include <cstdint>

#define B  4
#define N  65536
#define M  128
#define K_POS 128
#define K_NEG 384
#define NSAMP 512

// Output layout (float32, tuple flattened in order)
#define OFF_ROIS 0
#define OFF_LAB  (B*NSAMP*8)              // 16384
#define OFF_VAL  (OFF_LAB + B*NSAMP)      // 18432
#define OFF_ASG  (OFF_VAL + B*NSAMP)      // 20480
#define OFF_MAX  (OFF_ASG + B*N)          // 282624

#define HI_CAP   (1<<18)
#define CAND_CAP 4096
#define NBIN     2048
#define FBLOCKS  ((N/2048)*B)             // finalize grid size = 128

// Scratch: zero-initialized at load; every consumer resets what it reads so
// graph replays see identical initial state.
__device__ int      g_assigned[B * N];
__device__ unsigned g_lqv[B * N];            // M - m of first matching gt; 0 = none
__device__ uint2    g_hi[B][HI_CAP];         // (n | m<<16, iou_bits) for iou>=0.5
__device__ int      g_hicnt[B];
__device__ unsigned g_hist[8 * NBIN];
__device__ int      g_bt[8];
__device__ unsigned g_fdone;
__device__ unsigned long long g_cand[8][CAND_CAP];
__device__ int      g_ccnt[8];

__device__ __forceinline__ void st(float* out, long long idx, float v, long long lim) {
    if (idx < lim) out[idx] = v;
}

// Exact IoU matching the JAX op sequence (validated rel_err==0).
__device__ __forceinline__ float iou_exact(float4 bb, float ab, float4 g, float ag) {
    float ltx = fmaxf(bb.x, g.x);
    float lty = fmaxf(bb.y, g.y);
    float rbx = fminf(bb.z, g.z);
    float rby = fminf(bb.w, g.w);
    float w = fmaxf(__fsub_rn(rbx, ltx), 0.0f);
    float h = fmaxf(__fsub_rn(rby, lty), 0.0f);
    float inter = __fmul_rn(w, h);
    float u = __fadd_rn(ab, ag);
    u = __fsub_rn(u, inter);
    u = __fadd_rn(u, 1e-6f);
    return __fdiv_rn(inter, u);
}

__device__ __forceinline__ void iou_parts(float4 bb, float ab, float4 g, float ag,
                                          float& inter, float& u) {
    float ltx = fmaxf(bb.x, g.x);
    float lty = fmaxf(bb.y, g.y);
    float rbx = fminf(bb.z, g.z);
    float rby = fminf(bb.w, g.w);
    float w = fmaxf(__fsub_rn(rbx, ltx), 0.0f);
    float h = fmaxf(__fsub_rn(rby, lty), 0.0f);
    inter = __fmul_rn(w, h);
    float uu = __fadd_rn(ab, ag);
    uu = __fsub_rn(uu, inter);
    u = __fadd_rn(uu, 1e-6f);
}

__device__ __forceinline__ int val_bin(float v) {
    int iv = (int)(__fmul_rn(v, 186.0f));   // v in [0, 11) -> [0, 2046]
    if (iv < 0) iv = 0;
    if (iv > NBIN - 1) iv = NBIN - 1;
    return iv;
}

// ---------------------------------------------------------------------------
// Division-free assignment, 4 boxes/thread, zero sync/atomic work in the loop.
// Pushes (iou>=0.5) deferred via a 16-bit group mask (8 gts per bit) and
// handled post-loop with exact divides (rare).
__global__ void __launch_bounds__(256)
assign_fused_kernel(const float4* __restrict__ bboxes,
                    const float4* __restrict__ gts,
                    float* __restrict__ out, long long lim) {
    __shared__ float4 sgt[M];
    __shared__ float  sga[M];
    int b = blockIdx.y;
    int tid = threadIdx.x;
    if (tid < M) {
        float4 g = gts[b * M + tid];
        sgt[tid] = g;
        sga[tid] = __fmul_rn(__fsub_rn(g.z, g.x), __fsub_rn(g.w, g.y));
    }
    __syncthreads();

    const int base = blockIdx.x * 1024;
    float4 bb[4];
    float ab[4], ib[4], ub[4];
    int bm[4];
    bool amb[4];
    unsigned pm[4];
#pragma unroll
    for (int k = 0; k < 4; k++) {
        int n = base + k * 256 + tid;
        bb[k] = bboxes[(long long)b * N + n];
        ab[k] = __fmul_rn(__fsub_rn(bb[k].z, bb[k].x), __fsub_rn(bb[k].w, bb[k].y));
        ib[k] = 0.0f; ub[k] = 1.0f; bm[k] = 0; amb[k] = false; pm[k] = 0u;
    }

#pragma unroll 4
    for (int m = 0; m < M; m++) {
        float4 g = sgt[m];
        float ag = sga[m];
        unsigned bit = 1u << (m >> 3);
#pragma unroll
        for (int k = 0; k < 4; k++) {
            float i, u;
            iou_parts(bb[k], ab[k], g, ag, i, u);
            float x = __fmul_rn(i, ub[k]);
            float y = __fmul_rn(ib[k], u);
            float d = __fsub_rn(x, y);
            // relative margin: zero-vs-zero gives threshold 0 -> no false amb
            amb[k] |= (fabsf(d) < __fmul_rn(fmaxf(x, y), 1.5e-6f));
            if (d > 0.0f) { ib[k] = i; ub[k] = u; bm[k] = m; }
            if (i >= __fmul_rn(u, 0.4999999f)) pm[k] |= bit;   // conservative
        }
    }

#pragma unroll
    for (int k = 0; k < 4; k++) {
        int n = base + k * 256 + tid;
        float q;
        int bmk = bm[k];
        if (amb[k]) {                       // rare: exact rerun
            float bq = -1.0f; int bmm = 0;
            for (int m = 0; m < M; m++) {
                float qq = iou_exact(bb[k], ab[k], sgt[m], sga[m]);
                if (qq > bq) { bq = qq; bmm = m; }
            }
            q = bq; bmk = bmm;
        } else {
            q = __fdiv_rn(ib[k], ub[k]);    // exact rounded quotient of winner
        }
        // deferred pushes: rescan flagged 8-wide groups with exact divides
        unsigned msk = pm[k];
        while (msk) {
            int gg = __ffs(msk) - 1;
            msk &= msk - 1;
            for (int mm = gg * 8; mm < gg * 8 + 8; mm++) {
                float i, u;
                iou_parts(bb[k], ab[k], sgt[mm], sga[mm], i, u);
                if (i >= __fmul_rn(u, 0.4999999f)) {
                    float qq = __fdiv_rn(i, u);
                    if (qq >= 0.5f) {
                        int p = atomicAdd(&g_hicnt[b], 1);
                        if (p < HI_CAP)
                            g_hi[b][p] = make_uint2((unsigned)n | ((unsigned)mm << 16),
                                                    __float_as_uint(qq));
                    }
                }
            }
        }
        long long o = (long long)b * N + n;
        g_assigned[o] = (q >= 0.5f) ? (bmk + 1) : 0;
        st(out, OFF_MAX + o, q, lim);
    }
}

// ---------------------------------------------------------------------------
// LQ match from candidates: reconstruct per-gt column max (exact where >=0.5),
// record first matching gt (max of M-m) per box.
__global__ void __launch_bounds__(1024)
lq_refine_kernel() {
    __shared__ unsigned sgm[M];
    int b = blockIdx.x;
    int tid = threadIdx.x;
    if (tid < M) sgm[tid] = 0u;
    __syncthreads();
    int c = g_hicnt[b];
    if (c > HI_CAP) c = HI_CAP;
    for (int i = tid; i < c; i += 1024) {
        uint2 e = g_hi[b][i];
        atomicMax(&sgm[e.x >> 16], e.y);
    }
    __syncthreads();
    for (int i = tid; i < c; i += 1024) {
        uint2 e = g_hi[b][i];
        unsigned m = e.x >> 16;
        if (e.y == sgm[m])
            atomicMax(&g_lqv[(long long)b * N + (e.x & 0xFFFFu)], (unsigned)(M - (int)m));
    }
    __syncthreads();
    if (tid == 0) g_hicnt[b] = 0;           // reset for next replay
}

// ---------------------------------------------------------------------------
// Finalize assignment + build both masked-value histograms; last block
// computes g_bt for all 8 tasks with one warp per task (shuffle suffix-scan).
__global__ void __launch_bounds__(512)
finalize_hist_kernel(const float* __restrict__ prio,
                     float* __restrict__ out, long long lim) {
    __shared__ unsigned hp[NBIN];
    __shared__ unsigned hn[NBIN];
    __shared__ int s_last;
    int b = blockIdx.y;
    int tid = threadIdx.x;
#pragma unroll
    for (int j = 0; j < NBIN / 512; j++) {
        hp[tid + j * 512] = 0u;
        hn[tid + j * 512] = 0u;
    }
    __syncthreads();
    const float* pr = prio + (long long)b * N;
#pragma unroll
    for (int j = 0; j < 4; j++) {
        int n = blockIdx.x * 2048 + j * 512 + tid;
        long long o = (long long)b * N + n;
        int a = g_assigned[o];
        unsigned lv = g_lqv[o];
        if (lv) { a = (M - (int)lv) + 1; g_lqv[o] = 0u; }   // apply + reset
        g_assigned[o] = a;
        st(out, OFF_ASG + o, (float)a, lim);
        float v = pr[n];
        float vp = (a > 0)  ? __fadd_rn(v, 10.0f) : v;
        float vn = (a == 0) ? __fadd_rn(v, 10.0f) : v;
        atomicAdd(&hp[val_bin(vp)], 1u);
        atomicAdd(&hn[val_bin(vn)], 1u);
    }
    __syncthreads();
#pragma unroll
    for (int j = 0; j < NBIN / 512; j++) {
        int k = tid + j * 512;
        unsigned vp = hp[k], vn = hn[k];
        if (vp) atomicAdd(&g_hist[(2 * b) * NBIN + k], vp);
        if (vn) atomicAdd(&g_hist[(2 * b + 1) * NBIN + k], vn);
    }
    __syncthreads();
    if (tid == 0) {
        __threadfence();
        s_last = (atomicAdd(&g_fdone, 1u) == FBLOCKS - 1) ? 1 : 0;
    }
    __syncthreads();
    if (!s_last) return;
    // ---- last block: one warp per task, shuffle suffix-scan over 2048 bins
    int w = tid >> 5, lane = tid & 31;
    if (w < 8) {
        int task = w;
        unsigned K = (task & 1) ? K_NEG : K_POS;
        const unsigned* h = &g_hist[task * NBIN];
        // lane covers bins [lane*64, lane*64+64)
        unsigned cs = 0;
        for (int j = 0; j < 64; j++) cs += h[lane * 64 + j];
        // inclusive suffix sum over lanes (lane..31)
        unsigned acc = cs;
        for (int off = 1; off < 32; off <<= 1) {
            unsigned v = __shfl_down_sync(0xffffffffu, acc, off);
            if (lane + off < 32) acc += v;
        }
        unsigned cum = acc - cs;            // count of bins in lanes > this one
        for (int d = lane * 64 + 63; d >= lane * 64; --d) {
            unsigned nc = cum + h[d];
            if (nc >= K && cum < K) g_bt[task] = d;
            cum = nc;
        }
    }
    __syncthreads();
    if (tid == 0) g_fdone = 0u;             // reset for next replay
}

// ---------------------------------------------------------------------------
// Single-scan compaction for both pos and neg tasks of a batch.
__global__ void __launch_bounds__(256)
compact_kernel(const float* __restrict__ prio) {
    int b = blockIdx.y;
    int btp = g_bt[2 * b];
    int btn = g_bt[2 * b + 1];
    const float* pr = prio + (long long)b * N;
    const int* asg = g_assigned + (long long)b * N;
    int base = blockIdx.x * 1024;
#pragma unroll
    for (int j = 0; j < 4; j++) {
        int n = base + j * 256 + threadIdx.x;
        int a = asg[n];
        float v = pr[n];
        float vp = (a > 0)  ? __fadd_rn(v, 10.0f) : v;
        float vn = (a == 0) ? __fadd_rn(v, 10.0f) : v;
        if (val_bin(vp) >= btp) {
            int p = atomicAdd(&g_ccnt[2 * b], 1);
            if (p < CAND_CAP)
                g_cand[2 * b][p] =
                    ((unsigned long long)__float_as_uint(vp) << 32)
                  | (unsigned long long)(0xFFFFFFFFu - (unsigned)n);
        }
        if (val_bin(vn) >= btn) {
            int p = atomicAdd(&g_ccnt[2 * b + 1], 1);
            if (p < CAND_CAP)
                g_cand[2 * b + 1][p] =
                    ((unsigned long long)__float_as_uint(vn) << 32)
                  | (unsigned long long)(0xFFFFFFFFu - (unsigned)n);
        }
    }
}

// ---------------------------------------------------------------------------
// Sort candidates desc (64-bit keys: value desc, index asc = JAX order), emit
// sampled rows. Resets hist/ccnt.
__global__ void __launch_bounds__(1024)
sortsel_gather_kernel(const float4* __restrict__ bboxes,
                      const float4* __restrict__ gts,
                      const int* __restrict__ labels,
                      float* __restrict__ out, long long lim) {
    __shared__ unsigned long long skeys[CAND_CAP];
    int task = blockIdx.x;
    int b = task >> 1, which = task & 1;
    int K = which ? K_NEG : K_POS;
    int tid = threadIdx.x;
    int nc = g_ccnt[task];
    if (nc > CAND_CAP) nc = CAND_CAP;
    int P = 512;
    while (P < nc) P <<= 1;
    for (int i = tid; i < P; i += 1024)
        skeys[i] = (i < nc) ? g_cand[task][i] : 0ULL;
    __syncthreads();
    for (int kk = 2; kk <= P; kk <<= 1) {
        for (int j = kk >> 1; j > 0; j >>= 1) {
            for (int i = tid; i < P; i += 1024) {
                int l = i ^ j;
                if (l > i) {
                    unsigned long long a = skeys[i], c = skeys[l];
                    bool desc = ((i & kk) == 0);
                    if (desc ? (a < c) : (a > c)) { skeys[i] = c; skeys[l] = a; }
                }
            }
            __syncthreads();
        }
    }
    for (int i = tid; i < K; i += 1024) {
        unsigned idx = 0xFFFFFFFFu - (unsigned)(skeys[i] & 0xFFFFFFFFull);
        float4 bb = bboxes[(long long)b * N + idx];
        int a = g_assigned[(long long)b * N + idx];
        float4 tgt = make_float4(0.f, 0.f, 0.f, 0.f);
        float lab, val;
        int row;
        if (!which) {
            row = i;
            bool v = (a > 0);
            int gi = a - 1; if (gi < 0) gi = 0;
            if (v) {
                tgt = gts[b * M + gi];
                lab = (float)labels[b * M + gi];
            } else {
                lab = -1.0f;
            }
            val = v ? 1.0f : 0.0f;
        } else {
            row = K_POS + i;
            lab = 0.0f;
            val = (a == 0) ? 1.0f : 0.0f;
        }
        long long r = (long long)(b * NSAMP + row);
        long long ro = OFF_ROIS + r * 8;
        st(out, ro + 0, bb.x, lim); st(out, ro + 1, bb.y, lim);
        st(out, ro + 2, bb.z, lim); st(out, ro + 3, bb.w, lim);
        st(out, ro + 4, tgt.x, lim); st(out, ro + 5, tgt.y, lim);
        st(out, ro + 6, tgt.z, lim); st(out, ro + 7, tgt.w, lim);
        st(out, OFF_LAB + r, lab, lim);
        st(out, OFF_VAL + r, val, lim);
    }
    __syncthreads();
    for (int i = tid; i < NBIN; i += 1024) g_hist[task * NBIN + i] = 0u;
    if (tid == 0) g_ccnt[task] = 0;
}

extern "C" void kernel_launch(void* const* d_in, const int* in_sizes, int n_in,
                              void* d_out, int out_size) {
    const float4* bboxes = (const float4*)d_in[0];   // [B,N,4] f32
    const float4* gts    = (const float4*)d_in[1];   // [B,M,4] f32
    const int*    labels = (const int*)d_in[2];      // [B,M] i32
    const float*  prio   = (const float*)d_in[3];    // [B,N] f32
    float* out = (float*)d_out;
    long long lim = (long long)out_size;

    assign_fused_kernel<<<dim3(N / 1024, B), 256>>>(bboxes, gts, out, lim);
    lq_refine_kernel<<<B, 1024>>>();
    finalize_hist_kernel<<<dim3(N / 2048, B), 512>>>(prio, out, lim);
    compact_kernel<<<dim3(N / 1024, B), 256>>>(prio);
    sortsel_gather_kernel<<<8, 1024>>>(bboxes, gts, labels, out, lim);
}

// round 6
// speedup vs baseline: 1.0588x; 1.0588x over previous
#include <cuda_runtime.h>
#include <cuda_bf16.h>
#include <cstdint>

#define B  4
#define N  65536
#define M  128
#define K_POS 128
#define K_NEG 384
#define NSAMP 512

// Output layout (float32, tuple flattened in order)
#define OFF_ROIS 0
#define OFF_LAB  (B*NSAMP*8)              // 16384
#define OFF_VAL  (OFF_LAB + B*NSAMP)      // 18432
#define OFF_ASG  (OFF_VAL + B*NSAMP)      // 20480
#define OFF_MAX  (OFF_ASG + B*N)          // 282624

#define HI_CAP   (1<<18)
#define CAND_CAP 4096
#define NBIN     2048
#define FBLOCKS  ((N/2048)*B)             // finalize grid size = 128

// Scratch: zero-initialized at load; every consumer resets what it reads so
// graph replays see identical initial state.
__device__ int      g_assigned[B * N];
__device__ unsigned g_lqv[B * N];            // M - m of first matching gt; 0 = none
__device__ uint2    g_hi[B][HI_CAP];         // (n | m<<16, iou_bits) for iou>=0.5
__device__ int      g_hicnt[B];
__device__ unsigned g_hist[8 * NBIN];
__device__ int      g_bt[8];
__device__ unsigned g_fdone;
__device__ unsigned long long g_cand[8][CAND_CAP];
__device__ int      g_ccnt[8];

__device__ __forceinline__ void st(float* out, long long idx, float v, long long lim) {
    if (idx < lim) out[idx] = v;
}

// Exact IoU matching the JAX op sequence (validated rel_err==0).
__device__ __forceinline__ float iou_exact(float4 bb, float ab, float4 g, float ag) {
    float ltx = fmaxf(bb.x, g.x);
    float lty = fmaxf(bb.y, g.y);
    float rbx = fminf(bb.z, g.z);
    float rby = fminf(bb.w, g.w);
    float w = fmaxf(__fsub_rn(rbx, ltx), 0.0f);
    float h = fmaxf(__fsub_rn(rby, lty), 0.0f);
    float inter = __fmul_rn(w, h);
    float u = __fadd_rn(ab, ag);
    u = __fsub_rn(u, inter);
    u = __fadd_rn(u, 1e-6f);
    return __fdiv_rn(inter, u);
}

__device__ __forceinline__ void iou_parts(float4 bb, float ab, float4 g, float ag,
                                          float& inter, float& u) {
    float ltx = fmaxf(bb.x, g.x);
    float lty = fmaxf(bb.y, g.y);
    float rbx = fminf(bb.z, g.z);
    float rby = fminf(bb.w, g.w);
    float w = fmaxf(__fsub_rn(rbx, ltx), 0.0f);
    float h = fmaxf(__fsub_rn(rby, lty), 0.0f);
    inter = __fmul_rn(w, h);
    float uu = __fadd_rn(ab, ag);
    uu = __fsub_rn(uu, inter);
    u = __fadd_rn(uu, 1e-6f);
}

__device__ __forceinline__ int val_bin(float v) {
    int iv = (int)(__fmul_rn(v, 186.0f));   // v in [0, 11) -> [0, 2046]
    if (iv < 0) iv = 0;
    if (iv > NBIN - 1) iv = NBIN - 1;
    return iv;
}

// ---------------------------------------------------------------------------
// Division-free assignment, 2 boxes/thread (R4 register shape), zero
// sync/atomic/branch work in the mainloop. Pushes (iou>=0.5) deferred via a
// 16-bit group mask (8 gts per bit), handled post-loop with exact divides.
__global__ void __launch_bounds__(256)
assign_fused_kernel(const float4* __restrict__ bboxes,
                    const float4* __restrict__ gts,
                    float* __restrict__ out, long long lim) {
    __shared__ float4 sgt[M];
    __shared__ float  sga[M];
    int b = blockIdx.y;
    int tid = threadIdx.x;
    if (tid < M) {
        float4 g = gts[b * M + tid];
        sgt[tid] = g;
        sga[tid] = __fmul_rn(__fsub_rn(g.z, g.x), __fsub_rn(g.w, g.y));
    }
    __syncthreads();

    int n0 = blockIdx.x * 512 + tid;
    int n1 = n0 + 256;
    float4 bb0 = bboxes[(long long)b * N + n0];
    float4 bb1 = bboxes[(long long)b * N + n1];
    float ab0 = __fmul_rn(__fsub_rn(bb0.z, bb0.x), __fsub_rn(bb0.w, bb0.y));
    float ab1 = __fmul_rn(__fsub_rn(bb1.z, bb1.x), __fsub_rn(bb1.w, bb1.y));
    float ib0 = 0.0f, ub0 = 1.0f, ib1 = 0.0f, ub1 = 1.0f;
    int bm0 = 0, bm1 = 0;
    bool amb0 = false, amb1 = false;
    unsigned pm0 = 0u, pm1 = 0u;

#pragma unroll 4
    for (int m = 0; m < M; m++) {
        float4 g = sgt[m];
        float ag = sga[m];
        unsigned bit = 1u << (m >> 3);
        float i0, u0, i1, u1;
        iou_parts(bb0, ab0, g, ag, i0, u0);
        iou_parts(bb1, ab1, g, ag, i1, u1);
        float x0 = __fmul_rn(i0, ub0), y0 = __fmul_rn(ib0, u0);
        float x1 = __fmul_rn(i1, ub1), y1 = __fmul_rn(ib1, u1);
        float d0 = __fsub_rn(x0, y0);
        float d1 = __fsub_rn(x1, y1);
        amb0 |= (fabsf(d0) < __fmul_rn(fmaxf(x0, y0), 1.5e-6f));
        amb1 |= (fabsf(d1) < __fmul_rn(fmaxf(x1, y1), 1.5e-6f));
        if (d0 > 0.0f) { ib0 = i0; ub0 = u0; bm0 = m; }
        if (d1 > 0.0f) { ib1 = i1; ub1 = u1; bm1 = m; }
        if (i0 >= __fmul_rn(u0, 0.4999999f)) pm0 |= bit;   // conservative
        if (i1 >= __fmul_rn(u1, 0.4999999f)) pm1 |= bit;
    }

#pragma unroll
    for (int k = 0; k < 2; k++) {
        int n       = k ? n1  : n0;
        float4 bbk  = k ? bb1 : bb0;
        float abk   = k ? ab1 : ab0;
        float ibk   = k ? ib1 : ib0;
        float ubk   = k ? ub1 : ub0;
        int bmk     = k ? bm1 : bm0;
        bool ambk   = k ? amb1 : amb0;
        unsigned msk = k ? pm1 : pm0;
        float q;
        if (ambk) {                          // rare: exact rerun
            float bq = -1.0f; int bmm = 0;
            for (int m = 0; m < M; m++) {
                float qq = iou_exact(bbk, abk, sgt[m], sga[m]);
                if (qq > bq) { bq = qq; bmm = m; }
            }
            q = bq; bmk = bmm;
        } else {
            q = __fdiv_rn(ibk, ubk);         // exact rounded quotient of winner
        }
        // deferred pushes: rescan flagged 8-wide groups with exact divides
        while (msk) {
            int gg = __ffs(msk) - 1;
            msk &= msk - 1;
            for (int mm = gg * 8; mm < gg * 8 + 8; mm++) {
                float i, u;
                iou_parts(bbk, abk, sgt[mm], sga[mm], i, u);
                if (i >= __fmul_rn(u, 0.4999999f)) {
                    float qq = __fdiv_rn(i, u);
                    if (qq >= 0.5f) {
                        int p = atomicAdd(&g_hicnt[b], 1);
                        if (p < HI_CAP)
                            g_hi[b][p] = make_uint2((unsigned)n | ((unsigned)mm << 16),
                                                    __float_as_uint(qq));
                    }
                }
            }
        }
        long long o = (long long)b * N + n;
        g_assigned[o] = (q >= 0.5f) ? (bmk + 1) : 0;
        st(out, OFF_MAX + o, q, lim);
    }
}

// ---------------------------------------------------------------------------
// LQ match from candidates: reconstruct per-gt column max (exact where >=0.5),
// record first matching gt (max of M-m) per box.
__global__ void __launch_bounds__(1024)
lq_refine_kernel() {
    __shared__ unsigned sgm[M];
    int b = blockIdx.x;
    int tid = threadIdx.x;
    if (tid < M) sgm[tid] = 0u;
    __syncthreads();
    int c = g_hicnt[b];
    if (c > HI_CAP) c = HI_CAP;
    for (int i = tid; i < c; i += 1024) {
        uint2 e = g_hi[b][i];
        atomicMax(&sgm[e.x >> 16], e.y);
    }
    __syncthreads();
    for (int i = tid; i < c; i += 1024) {
        uint2 e = g_hi[b][i];
        unsigned m = e.x >> 16;
        if (e.y == sgm[m])
            atomicMax(&g_lqv[(long long)b * N + (e.x & 0xFFFFu)], (unsigned)(M - (int)m));
    }
    __syncthreads();
    if (tid == 0) g_hicnt[b] = 0;           // reset for next replay
}

// ---------------------------------------------------------------------------
// Finalize assignment + build both masked-value histograms; last block
// computes g_bt for all 8 tasks with one warp per task (shuffle suffix-scan).
__global__ void __launch_bounds__(512)
finalize_hist_kernel(const float* __restrict__ prio,
                     float* __restrict__ out, long long lim) {
    __shared__ unsigned hp[NBIN];
    __shared__ unsigned hn[NBIN];
    __shared__ int s_last;
    int b = blockIdx.y;
    int tid = threadIdx.x;
#pragma unroll
    for (int j = 0; j < NBIN / 512; j++) {
        hp[tid + j * 512] = 0u;
        hn[tid + j * 512] = 0u;
    }
    __syncthreads();
    const float* pr = prio + (long long)b * N;
#pragma unroll
    for (int j = 0; j < 4; j++) {
        int n = blockIdx.x * 2048 + j * 512 + tid;
        long long o = (long long)b * N + n;
        int a = g_assigned[o];
        unsigned lv = g_lqv[o];
        if (lv) { a = (M - (int)lv) + 1; g_lqv[o] = 0u; }   // apply + reset
        g_assigned[o] = a;
        st(out, OFF_ASG + o, (float)a, lim);
        float v = pr[n];
        float vp = (a > 0)  ? __fadd_rn(v, 10.0f) : v;
        float vn = (a == 0) ? __fadd_rn(v, 10.0f) : v;
        atomicAdd(&hp[val_bin(vp)], 1u);
        atomicAdd(&hn[val_bin(vn)], 1u);
    }
    __syncthreads();
#pragma unroll
    for (int j = 0; j < NBIN / 512; j++) {
        int k = tid + j * 512;
        unsigned vp = hp[k], vn = hn[k];
        if (vp) atomicAdd(&g_hist[(2 * b) * NBIN + k], vp);
        if (vn) atomicAdd(&g_hist[(2 * b + 1) * NBIN + k], vn);
    }
    __syncthreads();
    if (tid == 0) {
        __threadfence();
        s_last = (atomicAdd(&g_fdone, 1u) == FBLOCKS - 1) ? 1 : 0;
    }
    __syncthreads();
    if (!s_last) return;
    // ---- last block: one warp per task, shuffle suffix-scan over 2048 bins
    int w = tid >> 5, lane = tid & 31;
    if (w < 8) {
        int task = w;
        unsigned K = (task & 1) ? K_NEG : K_POS;
        const unsigned* h = &g_hist[task * NBIN];
        unsigned cs = 0;
        for (int j = 0; j < 64; j++) cs += h[lane * 64 + j];
        unsigned acc = cs;
        for (int off = 1; off < 32; off <<= 1) {
            unsigned v = __shfl_down_sync(0xffffffffu, acc, off);
            if (lane + off < 32) acc += v;
        }
        unsigned cum = acc - cs;            // bins in lanes > this one
        for (int d = lane * 64 + 63; d >= lane * 64; --d) {
            unsigned nc = cum + h[d];
            if (nc >= K && cum < K) g_bt[task] = d;
            cum = nc;
        }
    }
    __syncthreads();
    if (tid == 0) g_fdone = 0u;             // reset for next replay
}

// ---------------------------------------------------------------------------
// Single-scan compaction for both pos and neg tasks; 512 blocks for occupancy.
__global__ void __launch_bounds__(256)
compact_kernel(const float* __restrict__ prio) {
    int b = blockIdx.y;
    int btp = g_bt[2 * b];
    int btn = g_bt[2 * b + 1];
    const float* pr = prio + (long long)b * N;
    const int* asg = g_assigned + (long long)b * N;
    int base = blockIdx.x * 512;
#pragma unroll
    for (int j = 0; j < 2; j++) {
        int n = base + j * 256 + threadIdx.x;
        int a = asg[n];
        float v = pr[n];
        float vp = (a > 0)  ? __fadd_rn(v, 10.0f) : v;
        float vn = (a == 0) ? __fadd_rn(v, 10.0f) : v;
        if (val_bin(vp) >= btp) {
            int p = atomicAdd(&g_ccnt[2 * b], 1);
            if (p < CAND_CAP)
                g_cand[2 * b][p] =
                    ((unsigned long long)__float_as_uint(vp) << 32)
                  | (unsigned long long)(0xFFFFFFFFu - (unsigned)n);
        }
        if (val_bin(vn) >= btn) {
            int p = atomicAdd(&g_ccnt[2 * b + 1], 1);
            if (p < CAND_CAP)
                g_cand[2 * b + 1][p] =
                    ((unsigned long long)__float_as_uint(vn) << 32)
                  | (unsigned long long)(0xFFFFFFFFu - (unsigned)n);
        }
    }
}

// ---------------------------------------------------------------------------
// Sort candidates desc (64-bit keys: value desc, index asc = JAX order), emit
// sampled rows. Resets hist/ccnt.
__global__ void __launch_bounds__(1024)
sortsel_gather_kernel(const float4* __restrict__ bboxes,
                      const float4* __restrict__ gts,
                      const int* __restrict__ labels,
                      float* __restrict__ out, long long lim) {
    __shared__ unsigned long long skeys[CAND_CAP];
    int task = blockIdx.x;
    int b = task >> 1, which = task & 1;
    int K = which ? K_NEG : K_POS;
    int tid = threadIdx.x;
    int nc = g_ccnt[task];
    if (nc > CAND_CAP) nc = CAND_CAP;
    int P = 512;
    while (P < nc) P <<= 1;
    for (int i = tid; i < P; i += 1024)
        skeys[i] = (i < nc) ? g_cand[task][i] : 0ULL;
    __syncthreads();
    for (int kk = 2; kk <= P; kk <<= 1) {
        for (int j = kk >> 1; j > 0; j >>= 1) {
            for (int i = tid; i < P; i += 1024) {
                int l = i ^ j;
                if (l > i) {
                    unsigned long long a = skeys[i], c = skeys[l];
                    bool desc = ((i & kk) == 0);
                    if (desc ? (a < c) : (a > c)) { skeys[i] = c; skeys[l] = a; }
                }
            }
            __syncthreads();
        }
    }
    for (int i = tid; i < K; i += 1024) {
        unsigned idx = 0xFFFFFFFFu - (unsigned)(skeys[i] & 0xFFFFFFFFull);
        float4 bb = bboxes[(long long)b * N + idx];
        int a = g_assigned[(long long)b * N + idx];
        float4 tgt = make_float4(0.f, 0.f, 0.f, 0.f);
        float lab, val;
        int row;
        if (!which) {
            row = i;
            bool v = (a > 0);
            int gi = a - 1; if (gi < 0) gi = 0;
            if (v) {
                tgt = gts[b * M + gi];
                lab = (float)labels[b * M + gi];
            } else {
                lab = -1.0f;
            }
            val = v ? 1.0f : 0.0f;
        } else {
            row = K_POS + i;
            lab = 0.0f;
            val = (a == 0) ? 1.0f : 0.0f;
        }
        long long r = (long long)(b * NSAMP + row);
        long long ro = OFF_ROIS + r * 8;
        st(out, ro + 0, bb.x, lim); st(out, ro + 1, bb.y, lim);
        st(out, ro + 2, bb.z, lim); st(out, ro + 3, bb.w, lim);
        st(out, ro + 4, tgt.x, lim); st(out, ro + 5, tgt.y, lim);
        st(out, ro + 6, tgt.z, lim); st(out, ro + 7, tgt.w, lim);
        st(out, OFF_LAB + r, lab, lim);
        st(out, OFF_VAL + r, val, lim);
    }
    __syncthreads();
    for (int i = tid; i < NBIN; i += 1024) g_hist[task * NBIN + i] = 0u;
    if (tid == 0) g_ccnt[task] = 0;
}

extern "C" void kernel_launch(void* const* d_in, const int* in_sizes, int n_in,
                              void* d_out, int out_size) {
    const float4* bboxes = (const float4*)d_in[0];   // [B,N,4] f32
    const float4* gts    = (const float4*)d_in[1];   // [B,M,4] f32
    const int*    labels = (const int*)d_in[2];      // [B,M] i32
    const float*  prio   = (const float*)d_in[3];    // [B,N] f32
    float* out = (float*)d_out;
    long long lim = (long long)out_size;

    assign_fused_kernel<<<dim3(N / 512, B), 256>>>(bboxes, gts, out, lim);
    lq_refine_kernel<<<B, 1024>>>();
    finalize_hist_kernel<<<dim3(N / 2048, B), 512>>>(prio, out, lim);
    compact_kernel<<<dim3(N / 512, B), 256>>>(prio);
    sortsel_gather_kernel<<<8, 1024>>>(bboxes, gts, labels, out, lim);
}

// round 7
// speedup vs baseline: 1.1313x; 1.0684x over previous
#include <cuda_runtime.h>
#include <cuda_bf16.h>
#include <cstdint>

#define B  4
#define N  65536
#define M  128
#define K_POS 128
#define K_NEG 384
#define NSAMP 512

// Output layout (float32, tuple flattened in order)
#define OFF_ROIS 0
#define OFF_LAB  (B*NSAMP*8)              // 16384
#define OFF_VAL  (OFF_LAB + B*NSAMP)      // 18432
#define OFF_ASG  (OFF_VAL + B*NSAMP)      // 20480
#define OFF_MAX  (OFF_ASG + B*N)          // 282624

#define HI_CAP   (1<<18)
#define CAND_CAP 4096
#define NBIN     2048
#define FBLK_X   32
#define FBLOCKS  (FBLK_X * B)             // 128 blocks <= 148 SMs -> one wave

// Scratch: zero-initialized at load; every consumer resets what it reads so
// graph replays see identical initial state.
__device__ int      g_assigned[B * N];
__device__ unsigned g_lqv[B * N];            // M - m of first matching gt; 0 = none
__device__ uint2    g_hi[B][HI_CAP];         // (n | m<<16, iou_bits) for iou>=0.5
__device__ int      g_hicnt[B];
__device__ unsigned g_hist[8 * NBIN];
__device__ unsigned g_lqdone[B];
__device__ unsigned g_sync2, g_sync3;
__device__ unsigned long long g_cand[8][CAND_CAP];
__device__ int      g_ccnt[8];

__device__ __forceinline__ void st(float* out, long long idx, float v, long long lim) {
    if (idx < lim) out[idx] = v;
}

// Exact IoU matching the JAX op sequence (validated rel_err==0).
__device__ __forceinline__ float iou_exact(float4 bb, float ab, float4 g, float ag) {
    float ltx = fmaxf(bb.x, g.x);
    float lty = fmaxf(bb.y, g.y);
    float rbx = fminf(bb.z, g.z);
    float rby = fminf(bb.w, g.w);
    float w = fmaxf(__fsub_rn(rbx, ltx), 0.0f);
    float h = fmaxf(__fsub_rn(rby, lty), 0.0f);
    float inter = __fmul_rn(w, h);
    float u = __fadd_rn(ab, ag);
    u = __fsub_rn(u, inter);
    u = __fadd_rn(u, 1e-6f);
    return __fdiv_rn(inter, u);
}

__device__ __forceinline__ void iou_parts(float4 bb, float ab, float4 g, float ag,
                                          float& inter, float& u) {
    float ltx = fmaxf(bb.x, g.x);
    float lty = fmaxf(bb.y, g.y);
    float rbx = fminf(bb.z, g.z);
    float rby = fminf(bb.w, g.w);
    float w = fmaxf(__fsub_rn(rbx, ltx), 0.0f);
    float h = fmaxf(__fsub_rn(rby, lty), 0.0f);
    inter = __fmul_rn(w, h);
    float uu = __fadd_rn(ab, ag);
    uu = __fsub_rn(uu, inter);
    u = __fadd_rn(uu, 1e-6f);
}

__device__ __forceinline__ int val_bin(float v) {
    int iv = (int)(__fmul_rn(v, 186.0f));   // v in [0, 11) -> [0, 2046]
    if (iv < 0) iv = 0;
    if (iv > NBIN - 1) iv = NBIN - 1;
    return iv;
}

// ---------------------------------------------------------------------------
// R4 assignment kernel (measured best): division-free mainloop with in-loop
// ballot-aggregated pushes; cross-mult compare + ambiguity margin; rare
// ambiguous lanes rerun exactly.
__global__ void __launch_bounds__(256)
assign_fused_kernel(const float4* __restrict__ bboxes,
                    const float4* __restrict__ gts,
                    float* __restrict__ out, long long lim) {
    __shared__ float4 sgt[M];
    __shared__ float  sga[M];
    int b = blockIdx.y;
    int tid = threadIdx.x;
    if (tid < M) {
        float4 g = gts[b * M + tid];
        sgt[tid] = g;
        sga[tid] = __fmul_rn(__fsub_rn(g.z, g.x), __fsub_rn(g.w, g.y));
    }
    __syncthreads();
    int n0 = blockIdx.x * 512 + tid;
    int n1 = n0 + 256;
    float4 bb0 = bboxes[(long long)b * N + n0];
    float4 bb1 = bboxes[(long long)b * N + n1];
    float ab0 = __fmul_rn(__fsub_rn(bb0.z, bb0.x), __fsub_rn(bb0.w, bb0.y));
    float ab1 = __fmul_rn(__fsub_rn(bb1.z, bb1.x), __fsub_rn(bb1.w, bb1.y));
    float ib0 = 0.0f, ub0 = 1.0f, ib1 = 0.0f, ub1 = 1.0f;
    int bm0 = 0, bm1 = 0;
    bool amb0 = false, amb1 = false;
    int lane = tid & 31;
    unsigned lml = (1u << lane) - 1u;

#pragma unroll 4
    for (int m = 0; m < M; m++) {
        float4 g = sgt[m];
        float ag = sga[m];
        float i0, u0, i1, u1;
        iou_parts(bb0, ab0, g, ag, i0, u0);
        iou_parts(bb1, ab1, g, ag, i1, u1);
        float x0 = __fmul_rn(i0, ub0), y0 = __fmul_rn(ib0, u0);
        float x1 = __fmul_rn(i1, ub1), y1 = __fmul_rn(ib1, u1);
        float d0 = __fsub_rn(x0, y0);
        float d1 = __fsub_rn(x1, y1);
        amb0 |= (fabsf(d0) < __fmul_rn(fmaxf(x0, y0), 1.5e-6f));
        amb1 |= (fabsf(d1) < __fmul_rn(fmaxf(x1, y1), 1.5e-6f));
        if (d0 > 0.0f) { ib0 = i0; ub0 = u0; bm0 = m; }
        if (d1 > 0.0f) { ib1 = i1; ub1 = u1; bm1 = m; }
        bool p0 = (i0 >= __fmul_rn(u0, 0.4999999f));
        bool p1 = (i1 >= __fmul_rn(u1, 0.4999999f));
        if (__any_sync(0xffffffffu, p0 || p1)) {
            float q0 = p0 ? __fdiv_rn(i0, u0) : 0.0f;
            float q1 = p1 ? __fdiv_rn(i1, u1) : 0.0f;
            bool w0 = p0 && (q0 >= 0.5f);
            bool w1 = p1 && (q1 >= 0.5f);
            unsigned mk0 = __ballot_sync(0xffffffffu, w0);
            unsigned mk1 = __ballot_sync(0xffffffffu, w1);
            int c0 = __popc(mk0);
            int tot = c0 + __popc(mk1);
            int base = 0;
            if (lane == 0 && tot) base = atomicAdd(&g_hicnt[b], tot);
            base = __shfl_sync(0xffffffffu, base, 0);
            if (w0) {
                int p = base + __popc(mk0 & lml);
                if (p < HI_CAP)
                    g_hi[b][p] = make_uint2((unsigned)n0 | ((unsigned)m << 16),
                                            __float_as_uint(q0));
            }
            if (w1) {
                int p = base + c0 + __popc(mk1 & lml);
                if (p < HI_CAP)
                    g_hi[b][p] = make_uint2((unsigned)n1 | ((unsigned)m << 16),
                                            __float_as_uint(q1));
            }
        }
    }
    float q0, q1;
    if (amb0) {
        float bq = -1.0f; int bmm = 0;
        for (int m = 0; m < M; m++) {
            float q = iou_exact(bb0, ab0, sgt[m], sga[m]);
            if (q > bq) { bq = q; bmm = m; }
        }
        q0 = bq; bm0 = bmm;
    } else {
        q0 = __fdiv_rn(ib0, ub0);
    }
    if (amb1) {
        float bq = -1.0f; int bmm = 0;
        for (int m = 0; m < M; m++) {
            float q = iou_exact(bb1, ab1, sgt[m], sga[m]);
            if (q > bq) { bq = q; bmm = m; }
        }
        q1 = bq; bm1 = bmm;
    } else {
        q1 = __fdiv_rn(ib1, ub1);
    }
    long long o0 = (long long)b * N + n0;
    long long o1 = (long long)b * N + n1;
    g_assigned[o0] = (q0 >= 0.5f) ? (bm0 + 1) : 0;
    g_assigned[o1] = (q1 >= 0.5f) ? (bm1 + 1) : 0;
    st(out, OFF_MAX + o0, q0, lim);
    st(out, OFF_MAX + o1, q1, lim);
}

// ---------------------------------------------------------------------------
// Cooperative fused kernel: LQ refine (1 block/batch) -> finalize + hist ->
// grid barrier -> per-batch threshold bins -> register-resident compact.
// 128 blocks (one wave on 148 SMs) -> device-side spin barriers are safe.
__global__ void __launch_bounds__(512)
finalize_fused_kernel(const float* __restrict__ prio,
                      float* __restrict__ out, long long lim) {
    __shared__ unsigned hp[NBIN];
    __shared__ unsigned hn[NBIN];
    __shared__ unsigned sgm[M];
    __shared__ int s_btp, s_btn;
    int b = blockIdx.y;
    int tid = threadIdx.x;

#pragma unroll
    for (int j = 0; j < NBIN / 512; j++) {
        hp[tid + j * 512] = 0u;
        hn[tid + j * 512] = 0u;
    }
    if (tid == 0) { s_btp = 0; s_btn = 0; }

    // ---- phase 0: LQ refine (block x==0 of each batch); others wait
    if (blockIdx.x == 0) {
        if (tid < M) sgm[tid] = 0u;
        __syncthreads();
        int c = g_hicnt[b];
        if (c > HI_CAP) c = HI_CAP;
        for (int i = tid; i < c; i += 512) {
            uint2 e = g_hi[b][i];
            atomicMax(&sgm[e.x >> 16], e.y);
        }
        __syncthreads();
        for (int i = tid; i < c; i += 512) {
            uint2 e = g_hi[b][i];
            unsigned m = e.x >> 16;
            if (e.y == sgm[m])
                atomicMax(&g_lqv[(long long)b * N + (e.x & 0xFFFFu)],
                          (unsigned)(M - (int)m));
        }
        __syncthreads();
        if (tid == 0) {
            g_hicnt[b] = 0;                 // reset for next replay
            __threadfence();
            atomicExch(&g_lqdone[b], 1u);
        }
        __syncthreads();
    } else {
        if (tid == 0) {
            while (atomicAdd(&g_lqdone[b], 0u) == 0u) __nanosleep(64);
            __threadfence();
        }
        __syncthreads();
    }

    // ---- phase 1: finalize assigned + histograms (keep a, v in registers)
    const float* pr = prio + (long long)b * N;
    int   av[4];
    float vv[4];
#pragma unroll
    for (int j = 0; j < 4; j++) {
        int n = blockIdx.x * 2048 + j * 512 + tid;
        long long o = (long long)b * N + n;
        int a = g_assigned[o];
        unsigned lv = g_lqv[o];
        if (lv) { a = (M - (int)lv) + 1; g_lqv[o] = 0u; }   // apply + reset
        g_assigned[o] = a;
        st(out, OFF_ASG + o, (float)a, lim);
        float v = pr[n];
        av[j] = a; vv[j] = v;
        float vp = (a > 0)  ? __fadd_rn(v, 10.0f) : v;
        float vn = (a == 0) ? __fadd_rn(v, 10.0f) : v;
        atomicAdd(&hp[val_bin(vp)], 1u);
        atomicAdd(&hn[val_bin(vn)], 1u);
    }
    __syncthreads();
#pragma unroll
    for (int j = 0; j < NBIN / 512; j++) {
        int k = tid + j * 512;
        unsigned xp = hp[k], xn = hn[k];
        if (xp) atomicAdd(&g_hist[(2 * b) * NBIN + k], xp);
        if (xn) atomicAdd(&g_hist[(2 * b + 1) * NBIN + k], xn);
    }
    __syncthreads();

    // ---- grid barrier: all histograms complete
    if (tid == 0) {
        __threadfence();
        atomicAdd(&g_sync2, 1u);
        while (atomicAdd(&g_sync2, 0u) < (unsigned)FBLOCKS) __nanosleep(64);
        __threadfence();
    }
    __syncthreads();

    // ---- threshold bins for this batch's two tasks (warp 0: pos, warp 1: neg)
    int w = tid >> 5, lane = tid & 31;
    if (w < 2) {
        int task = 2 * b + w;
        unsigned K = (task & 1) ? K_NEG : K_POS;
        const unsigned* h = &g_hist[task * NBIN];
        unsigned cs = 0;
        for (int j = 0; j < 64; j++) cs += h[lane * 64 + j];
        unsigned acc = cs;
        for (int off = 1; off < 32; off <<= 1) {
            unsigned v = __shfl_down_sync(0xffffffffu, acc, off);
            if (lane + off < 32) acc += v;
        }
        unsigned cum = acc - cs;            // bins in lanes > this one
        for (int d = lane * 64 + 63; d >= lane * 64; --d) {
            unsigned nc = cum + h[d];
            if (nc >= K && cum < K) { if (w == 0) s_btp = d; else s_btn = d; }
            cum = nc;
        }
    }
    __syncthreads();
    int btp = s_btp, btn = s_btn;

    // ---- phase 2: compact from registers
#pragma unroll
    for (int j = 0; j < 4; j++) {
        int n = blockIdx.x * 2048 + j * 512 + tid;
        int a = av[j];
        float v = vv[j];
        float vp = (a > 0)  ? __fadd_rn(v, 10.0f) : v;
        float vn = (a == 0) ? __fadd_rn(v, 10.0f) : v;
        if (val_bin(vp) >= btp) {
            int p = atomicAdd(&g_ccnt[2 * b], 1);
            if (p < CAND_CAP)
                g_cand[2 * b][p] =
                    ((unsigned long long)__float_as_uint(vp) << 32)
                  | (unsigned long long)(0xFFFFFFFFu - (unsigned)n);
        }
        if (val_bin(vn) >= btn) {
            int p = atomicAdd(&g_ccnt[2 * b + 1], 1);
            if (p < CAND_CAP)
                g_cand[2 * b + 1][p] =
                    ((unsigned long long)__float_as_uint(vn) << 32)
                  | (unsigned long long)(0xFFFFFFFFu - (unsigned)n);
        }
    }

    // ---- exit barrier: last block resets sync state for next replay
    if (tid == 0) {
        unsigned r = atomicAdd(&g_sync3, 1u);
        if (r == (unsigned)(FBLOCKS - 1)) {
            g_sync2 = 0u;
            for (int i = 0; i < B; i++) g_lqdone[i] = 0u;
            __threadfence();
            g_sync3 = 0u;
        }
    }
}

// ---------------------------------------------------------------------------
// Sort candidates desc (64-bit keys: value desc, index asc = JAX order), emit
// sampled rows. Resets hist/ccnt.
__global__ void __launch_bounds__(1024)
sortsel_gather_kernel(const float4* __restrict__ bboxes,
                      const float4* __restrict__ gts,
                      const int* __restrict__ labels,
                      float* __restrict__ out, long long lim) {
    __shared__ unsigned long long skeys[CAND_CAP];
    int task = blockIdx.x;
    int b = task >> 1, which = task & 1;
    int K = which ? K_NEG : K_POS;
    int tid = threadIdx.x;
    int nc = g_ccnt[task];
    if (nc > CAND_CAP) nc = CAND_CAP;
    int P = 512;
    while (P < nc) P <<= 1;
    for (int i = tid; i < P; i += 1024)
        skeys[i] = (i < nc) ? g_cand[task][i] : 0ULL;
    __syncthreads();
    for (int kk = 2; kk <= P; kk <<= 1) {
        for (int j = kk >> 1; j > 0; j >>= 1) {
            for (int i = tid; i < P; i += 1024) {
                int l = i ^ j;
                if (l > i) {
                    unsigned long long a = skeys[i], c = skeys[l];
                    bool desc = ((i & kk) == 0);
                    if (desc ? (a < c) : (a > c)) { skeys[i] = c; skeys[l] = a; }
                }
            }
            __syncthreads();
        }
    }
    for (int i = tid; i < K; i += 1024) {
        unsigned idx = 0xFFFFFFFFu - (unsigned)(skeys[i] & 0xFFFFFFFFull);
        float4 bb = bboxes[(long long)b * N + idx];
        int a = g_assigned[(long long)b * N + idx];
        float4 tgt = make_float4(0.f, 0.f, 0.f, 0.f);
        float lab, val;
        int row;
        if (!which) {
            row = i;
            bool v = (a > 0);
            int gi = a - 1; if (gi < 0) gi = 0;
            if (v) {
                tgt = gts[b * M + gi];
                lab = (float)labels[b * M + gi];
            } else {
                lab = -1.0f;
            }
            val = v ? 1.0f : 0.0f;
        } else {
            row = K_POS + i;
            lab = 0.0f;
            val = (a == 0) ? 1.0f : 0.0f;
        }
        long long r = (long long)(b * NSAMP + row);
        long long ro = OFF_ROIS + r * 8;
        st(out, ro + 0, bb.x, lim); st(out, ro + 1, bb.y, lim);
        st(out, ro + 2, bb.z, lim); st(out, ro + 3, bb.w, lim);
        st(out, ro + 4, tgt.x, lim); st(out, ro + 5, tgt.y, lim);
        st(out, ro + 6, tgt.z, lim); st(out, ro + 7, tgt.w, lim);
        st(out, OFF_LAB + r, lab, lim);
        st(out, OFF_VAL + r, val, lim);
    }
    __syncthreads();
    for (int i = tid; i < NBIN; i += 1024) g_hist[task * NBIN + i] = 0u;
    if (tid == 0) g_ccnt[task] = 0;
}

extern "C" void kernel_launch(void* const* d_in, const int* in_sizes, int n_in,
                              void* d_out, int out_size) {
    const float4* bboxes = (const float4*)d_in[0];   // [B,N,4] f32
    const float4* gts    = (const float4*)d_in[1];   // [B,M,4] f32
    const int*    labels = (const int*)d_in[2];      // [B,M] i32
    const float*  prio   = (const float*)d_in[3];    // [B,N] f32
    float* out = (float*)d_out;
    long long lim = (long long)out_size;

    assign_fused_kernel<<<dim3(N / 512, B), 256>>>(bboxes, gts, out, lim);
    finalize_fused_kernel<<<dim3(FBLK_X, B), 512>>>(prio, out, lim);
    sortsel_gather_kernel<<<8, 1024>>>(bboxes, gts, labels, out, lim);
}

// round 8
// speedup vs baseline: 1.2852x; 1.1361x over previous
#include <cuda_runtime.h>
#include <cuda_bf16.h>
#include <cstdint>

#define B  4
#define N  65536
#define M  128
#define K_POS 128
#define K_NEG 384
#define NSAMP 512

// Output layout (float32, tuple flattened in order)
#define OFF_ROIS 0
#define OFF_LAB  (B*NSAMP*8)              // 16384
#define OFF_VAL  (OFF_LAB + B*NSAMP)      // 18432
#define OFF_ASG  (OFF_VAL + B*NSAMP)      // 20480
#define OFF_MAX  (OFF_ASG + B*N)          // 282624

#define HI_CAP   (1<<18)
#define CAND_CAP 4096
#define NBIN     2048
#define FBLK_X   32
#define FBLOCKS  (FBLK_X * B)             // 128 blocks <= 148 SMs -> one wave

// Scratch: zero-initialized at load; every consumer resets what it reads so
// graph replays see identical initial state.
__device__ int      g_assigned[B * N];
__device__ unsigned g_lqv[B * N];            // M - m of first matching gt; 0 = none
__device__ uint2    g_hi[B][HI_CAP];         // (n | m<<16, iou_bits) for iou>=0.5
__device__ int      g_hicnt[B];
__device__ unsigned g_hist[8 * NBIN];
__device__ unsigned g_lqdone[B];
__device__ unsigned g_sync2, g_sync3;
__device__ unsigned long long g_cand[8][CAND_CAP];
__device__ int      g_ccnt[8];

__device__ __forceinline__ void st(float* out, long long idx, float v, long long lim) {
    if (idx < lim) out[idx] = v;
}

// Exact IoU matching the JAX op sequence (validated rel_err==0).
__device__ __forceinline__ float iou_exact(float4 bb, float ab, float4 g, float ag) {
    float ltx = fmaxf(bb.x, g.x);
    float lty = fmaxf(bb.y, g.y);
    float rbx = fminf(bb.z, g.z);
    float rby = fminf(bb.w, g.w);
    float w = fmaxf(__fsub_rn(rbx, ltx), 0.0f);
    float h = fmaxf(__fsub_rn(rby, lty), 0.0f);
    float inter = __fmul_rn(w, h);
    float u = __fadd_rn(ab, ag);
    u = __fsub_rn(u, inter);
    u = __fadd_rn(u, 1e-6f);
    return __fdiv_rn(inter, u);
}

__device__ __forceinline__ void iou_parts(float4 bb, float ab, float4 g, float ag,
                                          float& inter, float& u) {
    float ltx = fmaxf(bb.x, g.x);
    float lty = fmaxf(bb.y, g.y);
    float rbx = fminf(bb.z, g.z);
    float rby = fminf(bb.w, g.w);
    float w = fmaxf(__fsub_rn(rbx, ltx), 0.0f);
    float h = fmaxf(__fsub_rn(rby, lty), 0.0f);
    inter = __fmul_rn(w, h);
    float uu = __fadd_rn(ab, ag);
    uu = __fsub_rn(uu, inter);
    u = __fadd_rn(uu, 1e-6f);
}

__device__ __forceinline__ int val_bin(float v) {
    int iv = (int)(__fmul_rn(v, 186.0f));   // v in [0, 11) -> [0, 2046]
    if (iv < 0) iv = 0;
    if (iv > NBIN - 1) iv = NBIN - 1;
    return iv;
}

// ---------------------------------------------------------------------------
// Assignment: 1 box/thread for max occupancy (1024 blocks). Division-free
// mainloop (cross-mult compare + x-relative ambiguity margin); rare ambiguous
// lanes rerun exactly; iou>=0.5 pushes are ballot-aggregated.
__global__ void __launch_bounds__(256)
assign_fused_kernel(const float4* __restrict__ bboxes,
                    const float4* __restrict__ gts,
                    float* __restrict__ out, long long lim) {
    __shared__ float4 sgt[M];
    __shared__ float  sga[M];
    int b = blockIdx.y;
    int tid = threadIdx.x;
    if (tid < M) {
        float4 g = gts[b * M + tid];
        sgt[tid] = g;
        sga[tid] = __fmul_rn(__fsub_rn(g.z, g.x), __fsub_rn(g.w, g.y));
    }
    __syncthreads();
    int n = blockIdx.x * 256 + tid;
    float4 bb = bboxes[(long long)b * N + n];
    float ab = __fmul_rn(__fsub_rn(bb.z, bb.x), __fsub_rn(bb.w, bb.y));
    float ib = 0.0f, ub = 1.0f;
    int bm = 0;
    bool amb = false;
    int lane = tid & 31;
    unsigned lml = (1u << lane) - 1u;

#pragma unroll 4
    for (int m = 0; m < M; m++) {
        float4 g = sgt[m];
        float ag = sga[m];
        float i, u;
        iou_parts(bb, ab, g, ag, i, u);
        float x = __fmul_rn(i, ub);
        float y = __fmul_rn(ib, u);
        float d = __fsub_rn(x, y);
        // x-relative margin: in the danger zone x ~= y so x ~= max(x,y);
        // x=0,y>0 is an unambiguous loss; x=y=0 -> margin 0 -> no false amb.
        amb |= (fabsf(d) < __fmul_rn(x, 1.5e-6f));
        if (d > 0.0f) { ib = i; ub = u; bm = m; }
        bool p = (i >= __fmul_rn(u, 0.4999999f));   // conservative pretest
        if (__any_sync(0xffffffffu, p)) {
            float q = p ? __fdiv_rn(i, u) : 0.0f;
            bool w = p && (q >= 0.5f);
            unsigned mk = __ballot_sync(0xffffffffu, w);
            int tot = __popc(mk);
            int base = 0;
            if (lane == 0 && tot) base = atomicAdd(&g_hicnt[b], tot);
            base = __shfl_sync(0xffffffffu, base, 0);
            if (w) {
                int p2 = base + __popc(mk & lml);
                if (p2 < HI_CAP)
                    g_hi[b][p2] = make_uint2((unsigned)n | ((unsigned)m << 16),
                                             __float_as_uint(q));
            }
        }
    }
    float q;
    if (amb) {                               // rare: exact rerun
        float bq = -1.0f; int bmm = 0;
        for (int m = 0; m < M; m++) {
            float qq = iou_exact(bb, ab, sgt[m], sga[m]);
            if (qq > bq) { bq = qq; bmm = m; }
        }
        q = bq; bm = bmm;
    } else {
        q = __fdiv_rn(ib, ub);               // exact rounded quotient of winner
    }
    long long o = (long long)b * N + n;
    g_assigned[o] = (q >= 0.5f) ? (bm + 1) : 0;
    st(out, OFF_MAX + o, q, lim);
}

// ---------------------------------------------------------------------------
// Cooperative fused kernel: LQ refine (1 block/batch) -> finalize + hist ->
// grid barrier -> per-batch threshold bins -> register-resident compact.
// 128 blocks (one wave on 148 SMs) -> device-side spin barriers are safe.
__global__ void __launch_bounds__(512)
finalize_fused_kernel(const float* __restrict__ prio,
                      float* __restrict__ out, long long lim) {
    __shared__ unsigned hp[NBIN];
    __shared__ unsigned hn[NBIN];
    __shared__ unsigned sgm[M];
    __shared__ int s_btp, s_btn;
    int b = blockIdx.y;
    int tid = threadIdx.x;

#pragma unroll
    for (int j = 0; j < NBIN / 512; j++) {
        hp[tid + j * 512] = 0u;
        hn[tid + j * 512] = 0u;
    }
    if (tid == 0) { s_btp = 0; s_btn = 0; }

    // ---- phase 0: LQ refine (block x==0 of each batch); others wait
    if (blockIdx.x == 0) {
        if (tid < M) sgm[tid] = 0u;
        __syncthreads();
        int c = g_hicnt[b];
        if (c > HI_CAP) c = HI_CAP;
        for (int i = tid; i < c; i += 512) {
            uint2 e = g_hi[b][i];
            atomicMax(&sgm[e.x >> 16], e.y);
        }
        __syncthreads();
        for (int i = tid; i < c; i += 512) {
            uint2 e = g_hi[b][i];
            unsigned m = e.x >> 16;
            if (e.y == sgm[m])
                atomicMax(&g_lqv[(long long)b * N + (e.x & 0xFFFFu)],
                          (unsigned)(M - (int)m));
        }
        __syncthreads();
        if (tid == 0) {
            g_hicnt[b] = 0;                 // reset for next replay
            __threadfence();
            atomicExch(&g_lqdone[b], 1u);
        }
        __syncthreads();
    } else {
        if (tid == 0) {
            while (atomicAdd(&g_lqdone[b], 0u) == 0u) __nanosleep(64);
            __threadfence();
        }
        __syncthreads();
    }

    // ---- phase 1: finalize assigned + histograms (keep a, v in registers)
    const float* pr = prio + (long long)b * N;
    int   av[4];
    float vv[4];
#pragma unroll
    for (int j = 0; j < 4; j++) {
        int n = blockIdx.x * 2048 + j * 512 + tid;
        long long o = (long long)b * N + n;
        int a = g_assigned[o];
        unsigned lv = g_lqv[o];
        if (lv) { a = (M - (int)lv) + 1; g_lqv[o] = 0u; }   // apply + reset
        g_assigned[o] = a;
        st(out, OFF_ASG + o, (float)a, lim);
        float v = pr[n];
        av[j] = a; vv[j] = v;
        float vp = (a > 0)  ? __fadd_rn(v, 10.0f) : v;
        float vn = (a == 0) ? __fadd_rn(v, 10.0f) : v;
        atomicAdd(&hp[val_bin(vp)], 1u);
        atomicAdd(&hn[val_bin(vn)], 1u);
    }
    __syncthreads();
#pragma unroll
    for (int j = 0; j < NBIN / 512; j++) {
        int k = tid + j * 512;
        unsigned xp = hp[k], xn = hn[k];
        if (xp) atomicAdd(&g_hist[(2 * b) * NBIN + k], xp);
        if (xn) atomicAdd(&g_hist[(2 * b + 1) * NBIN + k], xn);
    }
    __syncthreads();

    // ---- grid barrier: all histograms complete
    if (tid == 0) {
        __threadfence();
        atomicAdd(&g_sync2, 1u);
        while (atomicAdd(&g_sync2, 0u) < (unsigned)FBLOCKS) __nanosleep(64);
        __threadfence();
    }
    __syncthreads();

    // ---- threshold bins for this batch's two tasks (warp 0: pos, warp 1: neg)
    int w = tid >> 5, lane = tid & 31;
    if (w < 2) {
        int task = 2 * b + w;
        unsigned K = (task & 1) ? K_NEG : K_POS;
        const unsigned* h = &g_hist[task * NBIN];
        unsigned cs = 0;
        for (int j = 0; j < 64; j++) cs += h[lane * 64 + j];
        unsigned acc = cs;
        for (int off = 1; off < 32; off <<= 1) {
            unsigned v = __shfl_down_sync(0xffffffffu, acc, off);
            if (lane + off < 32) acc += v;
        }
        unsigned cum = acc - cs;            // bins in lanes > this one
        for (int d = lane * 64 + 63; d >= lane * 64; --d) {
            unsigned nc = cum + h[d];
            if (nc >= K && cum < K) { if (w == 0) s_btp = d; else s_btn = d; }
            cum = nc;
        }
    }
    __syncthreads();
    int btp = s_btp, btn = s_btn;

    // ---- phase 2: compact from registers
#pragma unroll
    for (int j = 0; j < 4; j++) {
        int n = blockIdx.x * 2048 + j * 512 + tid;
        int a = av[j];
        float v = vv[j];
        float vp = (a > 0)  ? __fadd_rn(v, 10.0f) : v;
        float vn = (a == 0) ? __fadd_rn(v, 10.0f) : v;
        if (val_bin(vp) >= btp) {
            int p = atomicAdd(&g_ccnt[2 * b], 1);
            if (p < CAND_CAP)
                g_cand[2 * b][p] =
                    ((unsigned long long)__float_as_uint(vp) << 32)
                  | (unsigned long long)(0xFFFFFFFFu - (unsigned)n);
        }
        if (val_bin(vn) >= btn) {
            int p = atomicAdd(&g_ccnt[2 * b + 1], 1);
            if (p < CAND_CAP)
                g_cand[2 * b + 1][p] =
                    ((unsigned long long)__float_as_uint(vn) << 32)
                  | (unsigned long long)(0xFFFFFFFFu - (unsigned)n);
        }
    }

    // ---- exit barrier: last block resets sync state for next replay
    if (tid == 0) {
        unsigned r = atomicAdd(&g_sync3, 1u);
        if (r == (unsigned)(FBLOCKS - 1)) {
            g_sync2 = 0u;
            for (int i = 0; i < B; i++) g_lqdone[i] = 0u;
            __threadfence();
            g_sync3 = 0u;
        }
    }
}

// ---------------------------------------------------------------------------
// Sort candidates desc (64-bit keys: value desc, index asc = JAX order), emit
// sampled rows. Resets hist/ccnt.
__global__ void __launch_bounds__(1024)
sortsel_gather_kernel(const float4* __restrict__ bboxes,
                      const float4* __restrict__ gts,
                      const int* __restrict__ labels,
                      float* __restrict__ out, long long lim) {
    __shared__ unsigned long long skeys[CAND_CAP];
    int task = blockIdx.x;
    int b = task >> 1, which = task & 1;
    int K = which ? K_NEG : K_POS;
    int tid = threadIdx.x;
    int nc = g_ccnt[task];
    if (nc > CAND_CAP) nc = CAND_CAP;
    int P = 512;
    while (P < nc) P <<= 1;
    for (int i = tid; i < P; i += 1024)
        skeys[i] = (i < nc) ? g_cand[task][i] : 0ULL;
    __syncthreads();
    for (int kk = 2; kk <= P; kk <<= 1) {
        for (int j = kk >> 1; j > 0; j >>= 1) {
            for (int i = tid; i < P; i += 1024) {
                int l = i ^ j;
                if (l > i) {
                    unsigned long long a = skeys[i], c = skeys[l];
                    bool desc = ((i & kk) == 0);
                    if (desc ? (a < c) : (a > c)) { skeys[i] = c; skeys[l] = a; }
                }
            }
            __syncthreads();
        }
    }
    for (int i = tid; i < K; i += 1024) {
        unsigned idx = 0xFFFFFFFFu - (unsigned)(skeys[i] & 0xFFFFFFFFull);
        float4 bb = bboxes[(long long)b * N + idx];
        int a = g_assigned[(long long)b * N + idx];
        float4 tgt = make_float4(0.f, 0.f, 0.f, 0.f);
        float lab, val;
        int row;
        if (!which) {
            row = i;
            bool v = (a > 0);
            int gi = a - 1; if (gi < 0) gi = 0;
            if (v) {
                tgt = gts[b * M + gi];
                lab = (float)labels[b * M + gi];
            } else {
                lab = -1.0f;
            }
            val = v ? 1.0f : 0.0f;
        } else {
            row = K_POS + i;
            lab = 0.0f;
            val = (a == 0) ? 1.0f : 0.0f;
        }
        long long r = (long long)(b * NSAMP + row);
        long long ro = OFF_ROIS + r * 8;
        st(out, ro + 0, bb.x, lim); st(out, ro + 1, bb.y, lim);
        st(out, ro + 2, bb.z, lim); st(out, ro + 3, bb.w, lim);
        st(out, ro + 4, tgt.x, lim); st(out, ro + 5, tgt.y, lim);
        st(out, ro + 6, tgt.z, lim); st(out, ro + 7, tgt.w, lim);
        st(out, OFF_LAB + r, lab, lim);
        st(out, OFF_VAL + r, val, lim);
    }
    __syncthreads();
    for (int i = tid; i < NBIN; i += 1024) g_hist[task * NBIN + i] = 0u;
    if (tid == 0) g_ccnt[task] = 0;
}

extern "C" void kernel_launch(void* const* d_in, const int* in_sizes, int n_in,
                              void* d_out, int out_size) {
    const float4* bboxes = (const float4*)d_in[0];   // [B,N,4] f32
    const float4* gts    = (const float4*)d_in[1];   // [B,M,4] f32
    const int*    labels = (const int*)d_in[2];      // [B,M] i32
    const float*  prio   = (const float*)d_in[3];    // [B,N] f32
    float* out = (float*)d_out;
    long long lim = (long long)out_size;

    assign_fused_kernel<<<dim3(N / 256, B), 256>>>(bboxes, gts, out, lim);
    finalize_fused_kernel<<<dim3(FBLK_X, B), 512>>>(prio, out, lim);
    sortsel_gather_kernel<<<8, 1024>>>(bboxes, gts, labels, out, lim);
}